// round 2
// baseline (speedup 1.0000x reference)
#include <cuda_runtime.h>
#include <cuda_fp16.h>
#include <mma.h>
#include <math.h>
#include <stdint.h>

using namespace nvcuda;

#define SEQ   512
#define BATCH 256
#define INSZ  256
#define HID   128
#define GATES 512
#define OUTSZ 1000
#define M_TOT (SEQ*BATCH)

// ------------- static device scratch (no allocations allowed) ---------------
__device__ __half  g_xh[M_TOT * INSZ];          // x in fp16          (134 MB)
__device__ __half  g_wih[GATES * INSZ];         // w_ih fp16, [n][k]
__device__ float   g_bias[GATES];               // b_ih + b_hh
__device__ __half2 g_whh2[(HID/2) * GATES];     // [k2][gate][col] half2 over k
__device__ float   g_xproj[(size_t)M_TOT * GATES];  // fp32 gate preacts (268 MB)
__device__ float   g_hlast[BATCH * HID];

// ------------------------- kernel: x -> fp16 --------------------------------
__global__ void k_convert_x(const float* __restrict__ x) {
    int i = blockIdx.x * blockDim.x + threadIdx.x;       // float4 index
    const float4* src = (const float4*)x;
    float4 v = src[i];
    __half2* dst = (__half2*)g_xh;
    dst[2*i]   = __floats2half2_rn(v.x, v.y);
    dst[2*i+1] = __floats2half2_rn(v.z, v.w);
}

// --------------------- kernel: weight prep ----------------------------------
__global__ void k_prep(const float* __restrict__ w_ih, const float* __restrict__ w_hh,
                       const float* __restrict__ b_ih, const float* __restrict__ b_hh) {
    int i = blockIdx.x * blockDim.x + threadIdx.x;
    if (i < GATES * INSZ) g_wih[i] = __float2half_rn(w_ih[i]);
    if (i < (HID/2) * GATES) {
        int k2 = i >> 9;            // half2 k index
        int j  = i & 511;           // gate*128+col
        g_whh2[i] = __floats2half2_rn(w_hh[j*HID + 2*k2], w_hh[j*HID + 2*k2 + 1]);
    }
    if (i < GATES) g_bias[i] = b_ih[i] + b_hh[i];
}

// ------------- kernel: xproj = Xh @ Wih^T + bias  (HMMA via WMMA) -----------
// CTA tile 128m x 64n; 8 warps as 4m x 2n, each warp 32x32 (2x2 frags).
__global__ void __launch_bounds__(256) k_gemm() {
    __shared__ float Cs[128 * 64];
    int warp = threadIdx.x >> 5;
    int wm = warp >> 1;                 // 0..3
    int wn = warp & 1;                  // 0..1
    int m0 = blockIdx.y * 128;
    int n0 = blockIdx.x * 64;

    wmma::fragment<wmma::accumulator, 16, 16, 16, float> c[2][2];
#pragma unroll
    for (int i = 0; i < 2; i++)
#pragma unroll
        for (int j = 0; j < 2; j++) wmma::fill_fragment(c[i][j], 0.0f);

    for (int kt = 0; kt < 16; kt++) {
        int k = kt * 16;
        wmma::fragment<wmma::matrix_a, 16, 16, 16, __half, wmma::row_major> a[2];
        wmma::fragment<wmma::matrix_b, 16, 16, 16, __half, wmma::col_major> b[2];
#pragma unroll
        for (int i = 0; i < 2; i++)
            wmma::load_matrix_sync(a[i], g_xh + (size_t)(m0 + wm*32 + i*16) * INSZ + k, INSZ);
#pragma unroll
        for (int j = 0; j < 2; j++)
            wmma::load_matrix_sync(b[j], g_wih + (size_t)(n0 + wn*32 + j*16) * INSZ + k, INSZ);
#pragma unroll
        for (int i = 0; i < 2; i++)
#pragma unroll
            for (int j = 0; j < 2; j++)
                wmma::mma_sync(c[i][j], a[i], b[j], c[i][j]);
    }

#pragma unroll
    for (int i = 0; i < 2; i++)
#pragma unroll
        for (int j = 0; j < 2; j++)
            wmma::store_matrix_sync(&Cs[(wm*32 + i*16) * 64 + wn*32 + j*16],
                                    c[i][j], 64, wmma::mem_row_major);
    __syncthreads();

    // bias add + coalesced float4 store
    for (int t = threadIdx.x; t < 128 * 16; t += 256) {   // 16 float4 per row
        int r  = t >> 4;
        int cq = t & 15;
        float4 v = ((float4*)Cs)[r * 16 + cq];
        int c0 = cq * 4;
        v.x += g_bias[n0 + c0];
        v.y += g_bias[n0 + c0 + 1];
        v.z += g_bias[n0 + c0 + 2];
        v.w += g_bias[n0 + c0 + 3];
        ((float4*)(g_xproj + (size_t)(m0 + r) * GATES + n0))[cq] = v;
    }
}

// --------------------- kernel: LSTM recurrence ------------------------------
// 128 CTAs x 256 threads. CTA owns 2 batch rows. Thread owns one (b,col):
// computes all 4 gate accumulators for that hidden column. w_hh (fp16) in
// SMEM; h double-buffered in SMEM; c in a register. One bar.sync per step.
extern __shared__ char rsm[];
__global__ void __launch_bounds__(256, 1) k_recur() {
    __half2* wsh = (__half2*)rsm;                      // [64][4][128] = 128 KB
    float*   hsh = (float*)(rsm + 131072);             // [2][2][128]
    int tid = threadIdx.x;
    int b   = tid >> 7;            // 0..1
    int col = tid & 127;
    int bg  = blockIdx.x * 2 + b;  // global batch row

    for (int i = tid; i < (HID/2) * GATES; i += 256) wsh[i] = g_whh2[i];
    hsh[tid] = 0.0f;
    hsh[256 + tid] = 0.0f;
    __syncthreads();

    float c = 0.0f;
    float hn = 0.0f;
    int cur = 0;
    const __half2* wp = wsh + col;

    for (int t = 0; t < SEQ; t++) {
        const float* xpt = g_xproj + ((size_t)t * BATCH + bg) * GATES;
        float a0 = xpt[col];
        float a1 = xpt[128 + col];
        float a2 = xpt[256 + col];
        float a3 = xpt[384 + col];
        const float* hb = hsh + cur * 256 + b * 128;
#pragma unroll 8
        for (int k2 = 0; k2 < 64; k2++) {
            float2 h2 = *(const float2*)(hb + 2 * k2);
            float2 w0 = __half22float2(wp[(k2*4 + 0) * 128]);
            float2 w1 = __half22float2(wp[(k2*4 + 1) * 128]);
            float2 w2 = __half22float2(wp[(k2*4 + 2) * 128]);
            float2 w3 = __half22float2(wp[(k2*4 + 3) * 128]);
            a0 += h2.x * w0.x + h2.y * w0.y;
            a1 += h2.x * w1.x + h2.y * w1.y;
            a2 += h2.x * w2.x + h2.y * w2.y;
            a3 += h2.x * w3.x + h2.y * w3.y;
        }
        float ig = 1.0f / (1.0f + __expf(-a0));
        float fg = 1.0f / (1.0f + __expf(-a1));
        float gg = 2.0f / (1.0f + __expf(-2.0f * a2)) - 1.0f;   // tanh
        float og = 1.0f / (1.0f + __expf(-a3));
        c = fg * c + ig * gg;
        float hc = 2.0f / (1.0f + __expf(-2.0f * c)) - 1.0f;    // tanh
        hn = og * hc;
        hsh[(cur ^ 1) * 256 + b * 128 + col] = hn;
        __syncthreads();
        cur ^= 1;
    }
    g_hlast[bg * HID + col] = hn;
}

// ------------------ kernel: dense + softmax ---------------------------------
__global__ void __launch_bounds__(256) k_dense(const float* __restrict__ wd,
                                               const float* __restrict__ bd,
                                               float* __restrict__ out) {
    int b = blockIdx.x;
    int tid = threadIdx.x;
    int lane = tid & 31;
    int warp = tid >> 5;
    __shared__ float logits[OUTSZ];
    __shared__ float red[8];

    float4 hv = ((const float4*)(g_hlast + b * HID))[lane];

    for (int o = warp; o < OUTSZ; o += 8) {
        float4 wv = ((const float4*)(wd + (size_t)o * HID))[lane];
        float p = hv.x*wv.x + hv.y*wv.y + hv.z*wv.z + hv.w*wv.w;
#pragma unroll
        for (int s = 16; s; s >>= 1) p += __shfl_xor_sync(0xffffffffu, p, s);
        if (lane == 0) logits[o] = p + bd[o];
    }
    __syncthreads();

    float m = -1e30f;
    for (int i = tid; i < OUTSZ; i += 256) m = fmaxf(m, logits[i]);
#pragma unroll
    for (int s = 16; s; s >>= 1) m = fmaxf(m, __shfl_xor_sync(0xffffffffu, m, s));
    if (lane == 0) red[warp] = m;
    __syncthreads();
    m = red[0];
#pragma unroll
    for (int w = 1; w < 8; w++) m = fmaxf(m, red[w]);

    float s = 0.0f;
    for (int i = tid; i < OUTSZ; i += 256) {
        float e = __expf(logits[i] - m);
        logits[i] = e;
        s += e;
    }
#pragma unroll
    for (int sh = 16; sh; sh >>= 1) s += __shfl_xor_sync(0xffffffffu, s, sh);
    __syncthreads();                  // red reads (max) done before reuse
    if (lane == 0) red[warp] = s;
    __syncthreads();
    s = red[0] + red[1] + red[2] + red[3] + red[4] + red[5] + red[6] + red[7];
    float inv = 1.0f / s;
    for (int i = tid; i < OUTSZ; i += 256) out[b * OUTSZ + i] = logits[i] * inv;
}

// ----------------------------- launcher -------------------------------------
extern "C" void kernel_launch(void* const* d_in, const int* in_sizes, int n_in,
                              void* d_out, int out_size) {
    const float* x   = (const float*)d_in[0];
    const float* wih = (const float*)d_in[1];
    const float* whh = (const float*)d_in[2];
    const float* bih = (const float*)d_in[3];
    const float* bhh = (const float*)d_in[4];
    const float* wd  = (const float*)d_in[5];
    const float* bd  = (const float*)d_in[6];
    float* out = (float*)d_out;

    cudaFuncSetAttribute(k_recur, cudaFuncAttributeMaxDynamicSharedMemorySize,
                         131072 + 2048);

    k_convert_x<<<(M_TOT * INSZ / 4) / 256, 256>>>(x);          // 32768 blocks
    k_prep<<<(GATES * INSZ) / 256, 256>>>(wih, whh, bih, bhh);  // 512 blocks
    k_gemm<<<dim3(GATES / 64, M_TOT / 128), 256>>>();           // (8, 1024)
    k_recur<<<BATCH / 2, 256, 131072 + 2048>>>();               // 128 blocks
    k_dense<<<BATCH, 256>>>(wd, bd, out);
}

// round 3
// speedup vs baseline: 1.1679x; 1.1679x over previous
#include <cuda_runtime.h>
#include <cuda_fp16.h>
#include <mma.h>
#include <math.h>
#include <stdint.h>
#include <stddef.h>

using namespace nvcuda;

#define SEQ   512
#define BATCH 256
#define INSZ  256
#define HID   128
#define GATES 512
#define OUTSZ 1000
#define M_TOT (SEQ*BATCH)

// ------------- static device scratch (no allocations allowed) ---------------
__device__ __half  g_wih[GATES * INSZ];             // w_ih fp16, [gate][k]
__device__ float   g_bias[GATES];                   // b_ih + b_hh
__device__ uint4   g_whh4[16 * 4 * 128];            // [k_blk][gate][col]: 8 halves over k
__device__ float   g_xproj[(size_t)M_TOT * GATES];  // fp32 gate preacts (268 MB)
__device__ float   g_hlast[BATCH * HID];

extern __shared__ char dynsm[];

// --------------------- kernel: weight prep ----------------------------------
__global__ void k_prep(const float* __restrict__ w_ih, const float* __restrict__ w_hh,
                       const float* __restrict__ b_ih, const float* __restrict__ b_hh) {
    int i = blockIdx.x * blockDim.x + threadIdx.x;
    if (i < GATES * INSZ) g_wih[i] = __float2half_rn(w_ih[i]);
    if (i < 16 * 4 * 128) {
        int kb  = i >> 9;          // 0..15
        int rem = i & 511;
        int g   = rem >> 7;        // 0..3
        int c   = rem & 127;
        const float* src = w_hh + (size_t)(g * 128 + c) * 128 + kb * 8;
        uint4 u;
        __half2* hp = (__half2*)&u;
        hp[0] = __floats2half2_rn(src[0], src[1]);
        hp[1] = __floats2half2_rn(src[2], src[3]);
        hp[2] = __floats2half2_rn(src[4], src[5]);
        hp[3] = __floats2half2_rn(src[6], src[7]);
        g_whh4[(kb * 4 + g) * 128 + c] = u;
    }
    if (i < GATES) g_bias[i] = b_ih[i] + b_hh[i];
}

// ------------- kernel: xproj = x @ w_ih^T + bias  (SMEM-staged WMMA) --------
// CTA: 128 m-rows. A tile [128][256] fp16 resident in SMEM (converted from
// fp32 x in-kernel). Loop over 8 n-tiles of 64 gates, B tile [64][256] fp16
// staged from L2-resident g_wih. 8 warps as 4m x 2n, warp 32x32 (2x2 frags).
__global__ void __launch_bounds__(256) k_gemm2(const float* __restrict__ x) {
    __half* As = (__half*)dynsm;                       // [128][256] = 64 KB
    __half* Bs = (__half*)(dynsm + 65536);             // [64][256]  = 32 KB
    float*  Cs = (float*)(dynsm + 65536 + 32768);      // [128][64]  = 32 KB
    int tid = threadIdx.x;
    int warp = tid >> 5;
    int wm = warp >> 1;                 // 0..3
    int wn = warp & 1;                  // 0..1
    int m0 = blockIdx.x * 128;

    // stage A with fp32 -> fp16 conversion (64 float4 per row)
    for (int idx = tid; idx < 128 * 64; idx += 256) {
        int row = idx >> 6;
        int q   = idx & 63;
        float4 v = ((const float4*)(x + (size_t)(m0 + row) * INSZ))[q];
        __half2* dst = (__half2*)(As + row * 256);
        dst[2 * q]     = __floats2half2_rn(v.x, v.y);
        dst[2 * q + 1] = __floats2half2_rn(v.z, v.w);
    }
    __syncthreads();

    for (int nt = 0; nt < 8; nt++) {
        int n0 = nt * 64;
        // stage B tile (32 uint4 per gate row)
        for (int idx = tid; idx < 64 * 32; idx += 256) {
            int row = idx >> 5;
            int q   = idx & 31;
            ((uint4*)(Bs + row * 256))[q] =
                ((const uint4*)(g_wih + (size_t)(n0 + row) * 256))[q];
        }
        __syncthreads();

        wmma::fragment<wmma::accumulator, 16, 16, 16, float> c[2][2];
#pragma unroll
        for (int i = 0; i < 2; i++)
#pragma unroll
            for (int j = 0; j < 2; j++) wmma::fill_fragment(c[i][j], 0.0f);

#pragma unroll
        for (int kt = 0; kt < 16; kt++) {
            int k = kt * 16;
            wmma::fragment<wmma::matrix_a, 16, 16, 16, __half, wmma::row_major> a[2];
            wmma::fragment<wmma::matrix_b, 16, 16, 16, __half, wmma::col_major> b[2];
#pragma unroll
            for (int i = 0; i < 2; i++)
                wmma::load_matrix_sync(a[i], As + (wm * 32 + i * 16) * 256 + k, 256);
#pragma unroll
            for (int j = 0; j < 2; j++)
                wmma::load_matrix_sync(b[j], Bs + (wn * 32 + j * 16) * 256 + k, 256);
#pragma unroll
            for (int i = 0; i < 2; i++)
#pragma unroll
                for (int j = 0; j < 2; j++)
                    wmma::mma_sync(c[i][j], a[i], b[j], c[i][j]);
        }

#pragma unroll
        for (int i = 0; i < 2; i++)
#pragma unroll
            for (int j = 0; j < 2; j++)
                wmma::store_matrix_sync(&Cs[(wm * 32 + i * 16) * 64 + wn * 32 + j * 16],
                                        c[i][j], 64, wmma::mem_row_major);
        __syncthreads();

        // bias add + coalesced float4 store
        for (int t = tid; t < 128 * 16; t += 256) {
            int r  = t >> 4;
            int cq = t & 15;
            float4 v = ((float4*)Cs)[r * 16 + cq];
            int c0 = cq * 4;
            v.x += g_bias[n0 + c0];
            v.y += g_bias[n0 + c0 + 1];
            v.z += g_bias[n0 + c0 + 2];
            v.w += g_bias[n0 + c0 + 3];
            ((float4*)(g_xproj + (size_t)(m0 + r) * GATES + n0))[cq] = v;
        }
        __syncthreads();   // before Bs/Cs reuse
    }
}

// --------------------- kernel: LSTM recurrence ------------------------------
// 128 CTAs x 256 threads, CTA owns 2 batch rows. Thread = (gate-pair gp, col):
//   gp=0 -> gates i(0), f(1);  gp=1 -> gates g(2), o(3).
// Each thread computes its 2 gates for BOTH batch rows (weights shared in
// registers). w_hh fp16 in SMEM, LDS.128 loads; h fp32 double-buffered in
// SMEM (broadcast loads); fp32 accumulation. Gate exchange via SMEM, two
// bar.syncs per step.
__global__ void __launch_bounds__(256, 1) k_recur2() {
    uint4* ws   = (uint4*)dynsm;                 // [kb][gate][col], 128 KB
    float* hbuf = (float*)(dynsm + 131072);      // [2][2][128]
    float* xch  = hbuf + 512;                    // [2 rows][{g,o}][128]
    int tid = threadIdx.x;
    int gp  = tid >> 7;            // 0..1
    int col = tid & 127;
    int g0  = gp * 2;
    int g1  = gp * 2 + 1;
    int r0  = blockIdx.x * 2;

    for (int i = tid; i < 16 * 4 * 128; i += 256) ws[i] = g_whh4[i];
    hbuf[tid] = 0.0f;              // zero h buffer 0 (256 floats)
    __syncthreads();

    float c0 = 0.0f, c1 = 0.0f, hn0 = 0.0f, hn1 = 0.0f;
    int cur = 0;
    const uint4* w0p = ws + g0 * 128 + col;
    const uint4* w1p = ws + g1 * 128 + col;

    for (int t = 0; t < SEQ; t++) {
        const float* xp = g_xproj + ((size_t)t * BATCH + r0) * GATES;
        // prefetch this step's 4 preact values (latency hidden by inner loop)
        float xA0 = xp[g0 * 128 + col];
        float xB0 = xp[g1 * 128 + col];
        float xA1 = xp[GATES + g0 * 128 + col];
        float xB1 = xp[GATES + g1 * 128 + col];

        const float* h0 = hbuf + cur * 256;
        const float* h1 = h0 + 128;
        float a00 = 0.0f, a01 = 0.0f, a10 = 0.0f, a11 = 0.0f;  // [gate][row]

#pragma unroll
        for (int kb = 0; kb < 16; kb++) {
            uint4 wA = w0p[kb * 512];
            uint4 wB = w1p[kb * 512];
            float4 p0 = *(const float4*)(h0 + kb * 8);
            float4 p1 = *(const float4*)(h0 + kb * 8 + 4);
            float4 q0 = *(const float4*)(h1 + kb * 8);
            float4 q1 = *(const float4*)(h1 + kb * 8 + 4);
            float2 wa0 = __half22float2(((const __half2*)&wA)[0]);
            float2 wa1 = __half22float2(((const __half2*)&wA)[1]);
            float2 wa2 = __half22float2(((const __half2*)&wA)[2]);
            float2 wa3 = __half22float2(((const __half2*)&wA)[3]);
            float2 wb0 = __half22float2(((const __half2*)&wB)[0]);
            float2 wb1 = __half22float2(((const __half2*)&wB)[1]);
            float2 wb2 = __half22float2(((const __half2*)&wB)[2]);
            float2 wb3 = __half22float2(((const __half2*)&wB)[3]);
            a00 += p0.x*wa0.x + p0.y*wa0.y + p0.z*wa1.x + p0.w*wa1.y
                 + p1.x*wa2.x + p1.y*wa2.y + p1.z*wa3.x + p1.w*wa3.y;
            a01 += q0.x*wa0.x + q0.y*wa0.y + q0.z*wa1.x + q0.w*wa1.y
                 + q1.x*wa2.x + q1.y*wa2.y + q1.z*wa3.x + q1.w*wa3.y;
            a10 += p0.x*wb0.x + p0.y*wb0.y + p0.z*wb1.x + p0.w*wb1.y
                 + p1.x*wb2.x + p1.y*wb2.y + p1.z*wb3.x + p1.w*wb3.y;
            a11 += q0.x*wb0.x + q0.y*wb0.y + q0.z*wb1.x + q0.w*wb1.y
                 + q1.x*wb2.x + q1.y*wb2.y + q1.z*wb3.x + q1.w*wb3.y;
        }
        a00 += xA0; a01 += xA1; a10 += xB0; a11 += xB1;

        if (gp == 1) {
            // gates: a0* = g (tanh), a1* = o (sigmoid)
            float gg0 = 2.0f / (1.0f + __expf(-2.0f * a00)) - 1.0f;
            float gg1 = 2.0f / (1.0f + __expf(-2.0f * a01)) - 1.0f;
            float oo0 = 1.0f / (1.0f + __expf(-a10));
            float oo1 = 1.0f / (1.0f + __expf(-a11));
            xch[col]       = gg0;
            xch[128 + col] = oo0;
            xch[256 + col] = gg1;
            xch[384 + col] = oo1;
        }
        __syncthreads();
        if (gp == 0) {
            // gates: a0* = i, a1* = f
            float i0 = 1.0f / (1.0f + __expf(-a00));
            float i1 = 1.0f / (1.0f + __expf(-a01));
            float f0 = 1.0f / (1.0f + __expf(-a10));
            float f1 = 1.0f / (1.0f + __expf(-a11));
            c0 = f0 * c0 + i0 * xch[col];
            c1 = f1 * c1 + i1 * xch[256 + col];
            hn0 = xch[128 + col] * (2.0f / (1.0f + __expf(-2.0f * c0)) - 1.0f);
            hn1 = xch[384 + col] * (2.0f / (1.0f + __expf(-2.0f * c1)) - 1.0f);
            hbuf[(cur ^ 1) * 256 + col]       = hn0;
            hbuf[(cur ^ 1) * 256 + 128 + col] = hn1;
        }
        __syncthreads();
        cur ^= 1;
    }
    if (gp == 0) {
        g_hlast[r0 * HID + col]       = hn0;
        g_hlast[(r0 + 1) * HID + col] = hn1;
    }
}

// ------------------ kernel: dense + softmax ---------------------------------
__global__ void __launch_bounds__(256) k_dense(const float* __restrict__ wd,
                                               const float* __restrict__ bd,
                                               float* __restrict__ out) {
    int b = blockIdx.x;
    int tid = threadIdx.x;
    int lane = tid & 31;
    int warp = tid >> 5;
    __shared__ float logits[OUTSZ];
    __shared__ float red[8];

    float4 hv = ((const float4*)(g_hlast + b * HID))[lane];

    for (int o = warp; o < OUTSZ; o += 8) {
        float4 wv = ((const float4*)(wd + (size_t)o * HID))[lane];
        float p = hv.x*wv.x + hv.y*wv.y + hv.z*wv.z + hv.w*wv.w;
#pragma unroll
        for (int s = 16; s; s >>= 1) p += __shfl_xor_sync(0xffffffffu, p, s);
        if (lane == 0) logits[o] = p + bd[o];
    }
    __syncthreads();

    float m = -1e30f;
    for (int i = tid; i < OUTSZ; i += 256) m = fmaxf(m, logits[i]);
#pragma unroll
    for (int s = 16; s; s >>= 1) m = fmaxf(m, __shfl_xor_sync(0xffffffffu, m, s));
    if (lane == 0) red[warp] = m;
    __syncthreads();
    m = red[0];
#pragma unroll
    for (int w = 1; w < 8; w++) m = fmaxf(m, red[w]);

    float s = 0.0f;
    for (int i = tid; i < OUTSZ; i += 256) {
        float e = __expf(logits[i] - m);
        logits[i] = e;
        s += e;
    }
#pragma unroll
    for (int sh = 16; sh; sh >>= 1) s += __shfl_xor_sync(0xffffffffu, s, sh);
    __syncthreads();
    if (lane == 0) red[warp] = s;
    __syncthreads();
    s = red[0] + red[1] + red[2] + red[3] + red[4] + red[5] + red[6] + red[7];
    float inv = 1.0f / s;
    for (int i = tid; i < OUTSZ; i += 256) out[b * OUTSZ + i] = logits[i] * inv;
}

// ----------------------------- launcher -------------------------------------
extern "C" void kernel_launch(void* const* d_in, const int* in_sizes, int n_in,
                              void* d_out, int out_size) {
    const float* x   = (const float*)d_in[0];
    const float* wih = (const float*)d_in[1];
    const float* whh = (const float*)d_in[2];
    const float* bih = (const float*)d_in[3];
    const float* bhh = (const float*)d_in[4];
    const float* wd  = (const float*)d_in[5];
    const float* bd  = (const float*)d_in[6];
    float* out = (float*)d_out;

    cudaFuncSetAttribute(k_gemm2,  cudaFuncAttributeMaxDynamicSharedMemorySize, 131072);
    cudaFuncSetAttribute(k_recur2, cudaFuncAttributeMaxDynamicSharedMemorySize, 131072 + 4096);

    k_prep<<<512, 256>>>(wih, whh, bih, bhh);
    k_gemm2<<<M_TOT / 128, 256, 131072>>>(x);
    k_recur2<<<BATCH / 2, 256, 131072 + 4096>>>();
    k_dense<<<BATCH, 256>>>(wd, bd, out);
}